// round 1
// baseline (speedup 1.0000x reference)
#include <cuda_runtime.h>
#include <cuda_bf16.h>

// LSTM cell, fully fused: g = x@U + h_old@W + bU + bW (4 gates), then
// elementwise LSTM update. B=65536, Din=256, H=512 (fixed shapes).
// fp32 SIMT baseline: BM=64 x BN=64 tile, TK=16, 256 threads,
// 4x4 micro-tile per thread x 4 gates = 64 accumulators.

#define DIN 256
#define HH  512
#define BM  64
#define BN  64
#define TK  16

__device__ __forceinline__ float sigmoid_f(float x) {
    return 1.0f / (1.0f + __expf(-x));
}

// One GEMM phase: acc[g][i][j] += A[bm0+row, :] . Wt[g, :, bn0+col]
// A is [B, K] row-major, Wt is [4, K, HH] (col index contiguous).
template<int K>
__device__ __forceinline__ void gemm_phase(
    const float* __restrict__ A, const float* __restrict__ Wt,
    int bm0, int bn0, int tid, int tx, int ty,
    float (&acc)[4][4][4], float (*As)[BM], float (*Bs)[TK][BN])
{
    const int arow = tid >> 2;       // 0..63
    const int akq  = tid & 3;        // 0..3 (which float4 along K)

    for (int kt = 0; kt < K; kt += TK) {
        // Load A tile [BM x TK], store transposed as As[k][m]
        float4 av = *reinterpret_cast<const float4*>(
            A + (size_t)(bm0 + arow) * K + kt + akq * 4);
        As[akq * 4 + 0][arow] = av.x;
        As[akq * 4 + 1][arow] = av.y;
        As[akq * 4 + 2][arow] = av.z;
        As[akq * 4 + 3][arow] = av.w;

        // Load weight tiles for all 4 gates: [4][TK][BN]
        #pragma unroll
        for (int i = 0; i < 4; i++) {
            int p   = tid + i * 256;       // float4 index in [4*16*16) space
            int g   = p >> 8;
            int rem = p & 255;
            int kk  = rem >> 4;
            int c4  = rem & 15;
            float4 bv = *reinterpret_cast<const float4*>(
                Wt + (size_t)g * K * HH + (size_t)(kt + kk) * HH + bn0 + c4 * 4);
            *reinterpret_cast<float4*>(&Bs[g][kk][c4 * 4]) = bv;
        }
        __syncthreads();

        #pragma unroll
        for (int kk = 0; kk < TK; kk++) {
            float4 a4 = *reinterpret_cast<const float4*>(&As[kk][ty * 4]);
            float ar[4] = {a4.x, a4.y, a4.z, a4.w};
            #pragma unroll
            for (int g = 0; g < 4; g++) {
                float4 b4 = *reinterpret_cast<const float4*>(&Bs[g][kk][tx * 4]);
                float br[4] = {b4.x, b4.y, b4.z, b4.w};
                #pragma unroll
                for (int ii = 0; ii < 4; ii++)
                    #pragma unroll
                    for (int jj = 0; jj < 4; jj++)
                        acc[g][ii][jj] = fmaf(ar[ii], br[jj], acc[g][ii][jj]);
            }
        }
        __syncthreads();
    }
}

__global__ __launch_bounds__(256, 2)
void lstm_fused_kernel(
    const float* __restrict__ X,    // [B, DIN]
    const float* __restrict__ Hin,  // [B, HH]
    const float* __restrict__ Cin,  // [B, HH]
    const float* __restrict__ U,    // [4, DIN, HH]
    const float* __restrict__ bU,   // [4, HH]
    const float* __restrict__ W,    // [4, HH, HH]
    const float* __restrict__ bW,   // [4, HH]
    float* __restrict__ out,        // [2, B, HH]  (h_new, c_new)
    int B)
{
    __shared__ float As[TK][BM];        // 4 KB
    __shared__ float Bs[4][TK][BN];     // 16 KB

    const int tid = threadIdx.x;
    const int tx  = tid & 15;           // 0..15 -> N micro
    const int ty  = tid >> 4;           // 0..15 -> M micro
    const int bn0 = blockIdx.x * BN;
    const int bm0 = blockIdx.y * BM;

    float acc[4][4][4];
    #pragma unroll
    for (int g = 0; g < 4; g++)
        #pragma unroll
        for (int i = 0; i < 4; i++)
            #pragma unroll
            for (int j = 0; j < 4; j++)
                acc[g][i][j] = 0.0f;

    // Phase A: x @ U   (K = DIN = 256)
    gemm_phase<DIN>(X, U, bm0, bn0, tid, tx, ty, acc, As, Bs);
    // Phase B: h_old @ W  (K = HH = 512)
    gemm_phase<HH>(Hin, W, bm0, bn0, tid, tx, ty, acc, As, Bs);

    // Epilogue: biases + gates + LSTM update; float4 over the N micro-tile
    const size_t BH = (size_t)B * HH;
    #pragma unroll
    for (int ii = 0; ii < 4; ii++) {
        const int brow = bm0 + ty * 4 + ii;
        const int hcol = bn0 + tx * 4;       // 4 contiguous columns
        float4 co4 = *reinterpret_cast<const float4*>(&Cin[(size_t)brow * HH + hcol]);
        float co[4] = {co4.x, co4.y, co4.z, co4.w};
        float hn[4], cn[4];
        #pragma unroll
        for (int jj = 0; jj < 4; jj++) {
            const int h = hcol + jj;
            float gi = acc[0][ii][jj] + bU[0 * HH + h] + bW[0 * HH + h];
            float gf = acc[1][ii][jj] + bU[1 * HH + h] + bW[1 * HH + h];
            float go = acc[2][ii][jj] + bU[2 * HH + h] + bW[2 * HH + h];
            float gc = acc[3][ii][jj] + bU[3 * HH + h] + bW[3 * HH + h];
            float it = sigmoid_f(gi);
            float ft = sigmoid_f(gf);
            float ot = sigmoid_f(go);
            float ct = tanhf(gc);
            float c  = fmaf(it, ct, ft * co[jj]);
            cn[jj] = c;
            hn[jj] = ot * tanhf(c);
        }
        *reinterpret_cast<float4*>(&out[(size_t)brow * HH + hcol]) =
            make_float4(hn[0], hn[1], hn[2], hn[3]);
        *reinterpret_cast<float4*>(&out[BH + (size_t)brow * HH + hcol]) =
            make_float4(cn[0], cn[1], cn[2], cn[3]);
    }
}

extern "C" void kernel_launch(void* const* d_in, const int* in_sizes, int n_in,
                              void* d_out, int out_size)
{
    const float* X   = (const float*)d_in[0];
    const float* Hin = (const float*)d_in[1];
    const float* Cin = (const float*)d_in[2];
    const float* U   = (const float*)d_in[3];
    const float* bU  = (const float*)d_in[4];
    const float* W   = (const float*)d_in[5];
    const float* bW  = (const float*)d_in[6];
    float* out = (float*)d_out;

    const int B = in_sizes[1] / HH;   // 65536
    dim3 grid(HH / BN, B / BM);       // (8, 1024)
    lstm_fused_kernel<<<grid, 256>>>(X, Hin, Cin, U, bU, W, bW, out, B);
}

// round 4
// speedup vs baseline: 4.1338x; 4.1338x over previous
#include <cuda_runtime.h>
#include <cuda_bf16.h>
#include <cstdint>

// ============================================================================
// LSTM cell via mma.sync bf16 (sm_103 base target — tcgen05 unavailable in
// this harness's PTX target), 3-pass bf16-split GEMM + fused LSTM epilogue.
// B=65536, Din=256, H=512 fixed.
// CTA: 128 batch x 128 cols (4 gates x 32 h). 8 warps (2M x 4N), warp 64x32.
// K pipeline: BK=64, 3-stage cp.async, 36 stages = 3 segments x (4 + 8).
// ============================================================================

#define BATCH 65536
#define DIN   256
#define HH    512
#define BM    128
#define BK    64
#define NSTAGE 36

// ---------------- device scratch --------------------------------------------
__device__ __nv_bfloat16 g_Xhi[BATCH * DIN];
__device__ __nv_bfloat16 g_Xlo[BATCH * DIN];
__device__ __nv_bfloat16 g_Hhi[BATCH * HH];
__device__ __nv_bfloat16 g_Hlo[BATCH * HH];
__device__ __nv_bfloat16 g_Uthi[4 * HH * DIN];   // [g][h][k] K-major
__device__ __nv_bfloat16 g_Utlo[4 * HH * DIN];
__device__ __nv_bfloat16 g_Wthi[4 * HH * HH];
__device__ __nv_bfloat16 g_Wtlo[4 * HH * HH];
__device__ float         g_bias[4 * HH];          // bU + bW

// ---------------- helpers ----------------------------------------------------
__device__ __forceinline__ uint32_t smem_u32(const void* p) {
    uint32_t a;
    asm("{ .reg .u64 t; cvta.to.shared.u64 t, %1; cvt.u32.u64 %0, t; }"
        : "=r"(a) : "l"(p));
    return a;
}
#define SW128(off) ((off) ^ (((off) >> 3) & 0x70))

__device__ __forceinline__ void cp16(uint32_t dst, const void* src) {
    asm volatile("cp.async.cg.shared.global [%0], [%1], 16;\n" :: "r"(dst), "l"(src));
}
#define CP_COMMIT() asm volatile("cp.async.commit_group;\n" ::: "memory")
#define CP_WAIT2()  asm volatile("cp.async.wait_group 2;\n" ::: "memory")
#define CP_WAIT1()  asm volatile("cp.async.wait_group 1;\n" ::: "memory")
#define CP_WAIT0()  asm volatile("cp.async.wait_group 0;\n" ::: "memory")

#define LDSM_X4(r0, r1, r2, r3, a)                                              \
    asm volatile("ldmatrix.sync.aligned.m8n8.x4.shared.b16 {%0,%1,%2,%3}, [%4];"\
        : "=r"(r0), "=r"(r1), "=r"(r2), "=r"(r3) : "r"(a))

__device__ __forceinline__ void mma16816(float* c, uint32_t a0, uint32_t a1,
                                         uint32_t a2, uint32_t a3,
                                         uint32_t b0, uint32_t b1) {
    asm volatile(
        "mma.sync.aligned.m16n8k16.row.col.f32.bf16.bf16.f32 "
        "{%0,%1,%2,%3}, {%4,%5,%6,%7}, {%8,%9}, {%0,%1,%2,%3};"
        : "+f"(c[0]), "+f"(c[1]), "+f"(c[2]), "+f"(c[3])
        : "r"(a0), "r"(a1), "r"(a2), "r"(a3), "r"(b0), "r"(b1));
}

// ---------------- SMEM layout ------------------------------------------------
// [0, 512)      bias (4 gates x 32 h floats)
// [1024, ...)   3 stage buffers; per stage: A 16KB + B 16KB = 32KB
// epilogue reuses [1024, 1024+73728): 4 planes of 128 x 36 floats
#define SM_STAGE(b) (1024 + (b) * 32768)
#define SMEM_TOTAL  (1024 + 3 * 32768)   // 99328
#define EP_BASE     1024
#define EP_PLANE    18432                // 128 * 36 * 4
#define EP_ROW      144                  // 36 floats

// ---------------- conversion kernels -----------------------------------------
__global__ void split_act_kernel(const float* __restrict__ src,
                                 __nv_bfloat16* __restrict__ hi,
                                 __nv_bfloat16* __restrict__ lo, int n4) {
    int i = blockIdx.x * blockDim.x + threadIdx.x;
    if (i >= n4) return;
    float4 v = reinterpret_cast<const float4*>(src)[i];
    float x[4] = {v.x, v.y, v.z, v.w};
    __nv_bfloat16 h[4], l[4];
    #pragma unroll
    for (int j = 0; j < 4; j++) {
        h[j] = __float2bfloat16_rn(x[j]);
        l[j] = __float2bfloat16_rn(x[j] - __bfloat162float(h[j]));
    }
    reinterpret_cast<uint2*>(hi)[i] = *reinterpret_cast<uint2*>(h);
    reinterpret_cast<uint2*>(lo)[i] = *reinterpret_cast<uint2*>(l);
}

template<int K>
__global__ void split_w_kernel(const float* __restrict__ src,   // [4, K, HH]
                               __nv_bfloat16* __restrict__ thi, // [4, HH, K]
                               __nv_bfloat16* __restrict__ tlo) {
    int i = blockIdx.x * blockDim.x + threadIdx.x;
    if (i >= 4 * HH * K) return;
    int k = i % K;
    int h = (i / K) % HH;
    int g = i / (K * HH);
    float x = src[((size_t)g * K + k) * HH + h];
    __nv_bfloat16 hh = __float2bfloat16_rn(x);
    thi[i] = hh;
    tlo[i] = __float2bfloat16_rn(x - __bfloat162float(hh));
}

__global__ void bias_kernel(const float* __restrict__ bU, const float* __restrict__ bW) {
    int i = blockIdx.x * blockDim.x + threadIdx.x;
    if (i < 4 * HH) g_bias[i] = bU[i] + bW[i];
}

// ---------------- stage source selection -------------------------------------
__device__ __forceinline__ void stage_src(int s, const __nv_bfloat16*& A,
                                          const __nv_bfloat16*& Bt, int& K, int& k0) {
    int seg = s / 12;
    int r = s - seg * 12;
    if (r < 4) {
        K = DIN; k0 = r * BK;
        A  = (seg == 1) ? g_Xlo  : g_Xhi;
        Bt = (seg == 2) ? g_Utlo : g_Uthi;
    } else {
        K = HH; k0 = (r - 4) * BK;
        A  = (seg == 1) ? g_Hlo  : g_Hhi;
        Bt = (seg == 2) ? g_Wtlo : g_Wthi;
    }
}

__device__ __forceinline__ void load_stage(uint32_t smem_base, int buf, int s,
                                           int bm0, int h0, int tid) {
    const __nv_bfloat16 *A, *Bt;
    int K, k0;
    stage_src(s, A, Bt, K, k0);
    uint32_t abase = smem_base + SM_STAGE(buf);
    // A tile: 128 rows x 64 k (128B/row), SW128
    #pragma unroll
    for (int i = 0; i < 4; i++) {
        int c = tid + i * 256;        // 0..1023 16B chunks
        int row = c >> 3, o = c & 7;
        cp16(abase + SW128(row * 128 + o * 16),
             A + (size_t)(bm0 + row) * K + k0 + o * 8);
    }
    // B tile: 128 rows (gate-major: row = g*32 + h_local) x 64 k
    uint32_t bbase = abase + 16384;
    #pragma unroll
    for (int i = 0; i < 4; i++) {
        int c = tid + i * 256;
        int row = c >> 3, o = c & 7;
        int g = row >> 5, hl = row & 31;
        cp16(bbase + SW128(row * 128 + o * 16),
             Bt + ((size_t)g * HH + h0 + hl) * K + k0 + o * 8);
    }
    CP_COMMIT();
}

// ---------------- main kernel -------------------------------------------------
__device__ __forceinline__ float sigmoid_f(float x) { return 1.0f / (1.0f + __expf(-x)); }
__device__ __forceinline__ float tanh_f(float x) {
    // accurate (~1e-7): tanh(x) = 1 - 2/(exp(2x)+1), stable both signs via |x|
    float ax = fabsf(x);
    float e = __expf(-2.0f * ax);
    float t = (1.0f - e) / (1.0f + e);
    return (x < 0.0f) ? -t : t;
}

__global__ void __launch_bounds__(256, 2)
lstm_mma_kernel(const float* __restrict__ Cin, float* __restrict__ out) {
    extern __shared__ char smem[];
    uint32_t smem_base = smem_u32(smem);
    float* bias_s = reinterpret_cast<float*>(smem);

    const int tid  = threadIdx.x;
    const int lane = tid & 31;
    const int w    = tid >> 5;
    const int wm   = (w >> 2) * 64;     // warp M offset
    const int nb   = (w & 3) * 32;      // warp N offset == gate*32
    const int h0   = blockIdx.x * 32;
    const int bm0  = blockIdx.y * BM;

    if (tid < 128)
        bias_s[tid] = g_bias[(tid >> 5) * HH + h0 + (tid & 31)];

    // fragment accumulators: [m-tile][n-tile][4]
    float acc[4][4][4];
    #pragma unroll
    for (int mi = 0; mi < 4; mi++)
        #pragma unroll
        for (int ni = 0; ni < 4; ni++)
            #pragma unroll
            for (int j = 0; j < 4; j++)
                acc[mi][ni][j] = 0.0f;

    // per-lane ldmatrix base offsets (bytes within tile, pre-swizzle)
    const int ar = wm + (lane & 15);
    const int aco = (lane >> 4) * 16;           // k byte offset within step
    int offA[4];
    #pragma unroll
    for (int mi = 0; mi < 4; mi++)
        offA[mi] = (ar + mi * 16) * 128 + aco;
    const int grp = lane >> 3;
    const int br = nb + (grp >> 1) * 8 + (lane & 7);
    const int bco = (grp & 1) * 16;
    int offB[2];
    #pragma unroll
    for (int j = 0; j < 2; j++)
        offB[j] = (br + j * 16) * 128 + bco;

    // prologue
    load_stage(smem_base, 0, 0, bm0, h0, tid);
    load_stage(smem_base, 1, 1, bm0, h0, tid);
    load_stage(smem_base, 2, 2, bm0, h0, tid);

    int buf = 0;
    for (int s = 0; s < NSTAGE; s++) {
        if (s < 34) CP_WAIT2();
        else if (s == 34) CP_WAIT1();
        else CP_WAIT0();
        __syncthreads();

        uint32_t ab = smem_base + SM_STAGE(buf);
        uint32_t bb = ab + 16384;
        #pragma unroll
        for (int ks = 0; ks < 4; ks++) {
            uint32_t a[4][4];
            #pragma unroll
            for (int mi = 0; mi < 4; mi++)
                LDSM_X4(a[mi][0], a[mi][1], a[mi][2], a[mi][3],
                        ab + SW128(offA[mi] + ks * 32));
            uint32_t b[2][4];
            #pragma unroll
            for (int j = 0; j < 2; j++)
                LDSM_X4(b[j][0], b[j][1], b[j][2], b[j][3],
                        bb + SW128(offB[j] + ks * 32));
            #pragma unroll
            for (int mi = 0; mi < 4; mi++)
                #pragma unroll
                for (int nt = 0; nt < 4; nt++)
                    mma16816(acc[mi][nt],
                             a[mi][0], a[mi][1], a[mi][2], a[mi][3],
                             b[nt >> 1][(nt & 1) * 2], b[nt >> 1][(nt & 1) * 2 + 1]);
        }
        __syncthreads();
        if (s + 3 < NSTAGE)
            load_stage(smem_base, buf, s + 3, bm0, h0, tid);
        buf = (buf == 2) ? 0 : buf + 1;
    }

    // ---------------- epilogue ------------------------------------------------
    // 1) exchange gates via SMEM planes: Ep[g][m][h] (row stride 36 floats)
    {
        const int g = w & 3;
        char* ep = smem + EP_BASE + g * EP_PLANE;
        #pragma unroll
        for (int mi = 0; mi < 4; mi++) {
            #pragma unroll
            for (int nt = 0; nt < 4; nt++) {
                int row = wm + mi * 16 + (lane >> 2);
                int col = nt * 8 + (lane & 3) * 2;
                *reinterpret_cast<float2*>(ep + row * EP_ROW + col * 4) =
                    make_float2(acc[mi][nt][0], acc[mi][nt][1]);
                *reinterpret_cast<float2*>(ep + (row + 8) * EP_ROW + col * 4) =
                    make_float2(acc[mi][nt][2], acc[mi][nt][3]);
            }
        }
    }
    __syncthreads();

    // 2) LSTM update: thread t handles m = t/2, h = (t&1)*16 .. +16
    {
        const int m_loc = tid >> 1;
        const int hb = (tid & 1) * 16;
        const int m = bm0 + m_loc;
        const size_t BHo = (size_t)BATCH * HH;
        const char* ep = smem + EP_BASE;
        #pragma unroll
        for (int hq = 0; hq < 4; hq++) {
            const int h = hb + hq * 4;
            float4 gi = *reinterpret_cast<const float4*>(ep + 0 * EP_PLANE + m_loc * EP_ROW + h * 4);
            float4 gf = *reinterpret_cast<const float4*>(ep + 1 * EP_PLANE + m_loc * EP_ROW + h * 4);
            float4 go = *reinterpret_cast<const float4*>(ep + 2 * EP_PLANE + m_loc * EP_ROW + h * 4);
            float4 gc = *reinterpret_cast<const float4*>(ep + 3 * EP_PLANE + m_loc * EP_ROW + h * 4);
            float4 co = *reinterpret_cast<const float4*>(&Cin[(size_t)m * HH + h0 + h]);
            float vi[4] = {gi.x, gi.y, gi.z, gi.w};
            float vf[4] = {gf.x, gf.y, gf.z, gf.w};
            float vo[4] = {go.x, go.y, go.z, go.w};
            float vc[4] = {gc.x, gc.y, gc.z, gc.w};
            float vold[4] = {co.x, co.y, co.z, co.w};
            float hn[4], cn[4];
            #pragma unroll
            for (int j = 0; j < 4; j++) {
                int cj = h + j;
                float it = sigmoid_f(vi[j] + bias_s[0 * 32 + cj]);
                float ft = sigmoid_f(vf[j] + bias_s[1 * 32 + cj]);
                float ot = sigmoid_f(vo[j] + bias_s[2 * 32 + cj]);
                float ct = tanh_f(vc[j] + bias_s[3 * 32 + cj]);
                float c  = fmaf(it, ct, ft * vold[j]);
                cn[j] = c;
                hn[j] = ot * tanh_f(c);
            }
            *reinterpret_cast<float4*>(&out[(size_t)m * HH + h0 + h]) =
                make_float4(hn[0], hn[1], hn[2], hn[3]);
            *reinterpret_cast<float4*>(&out[BHo + (size_t)m * HH + h0 + h]) =
                make_float4(cn[0], cn[1], cn[2], cn[3]);
        }
    }
}

// ---------------- launch ------------------------------------------------------
extern "C" void kernel_launch(void* const* d_in, const int* in_sizes, int n_in,
                              void* d_out, int out_size) {
    const float* X   = (const float*)d_in[0];
    const float* Hin = (const float*)d_in[1];
    const float* Cin = (const float*)d_in[2];
    const float* U   = (const float*)d_in[3];
    const float* bU  = (const float*)d_in[4];
    const float* W   = (const float*)d_in[5];
    const float* bW  = (const float*)d_in[6];
    float* out = (float*)d_out;

    cudaFuncSetAttribute(lstm_mma_kernel,
                         cudaFuncAttributeMaxDynamicSharedMemorySize, SMEM_TOTAL);

    __nv_bfloat16 *xhi, *xlo, *hhi, *hlo, *uthi, *utlo, *wthi, *wtlo;
    cudaGetSymbolAddress((void**)&xhi,  g_Xhi);
    cudaGetSymbolAddress((void**)&xlo,  g_Xlo);
    cudaGetSymbolAddress((void**)&hhi,  g_Hhi);
    cudaGetSymbolAddress((void**)&hlo,  g_Hlo);
    cudaGetSymbolAddress((void**)&uthi, g_Uthi);
    cudaGetSymbolAddress((void**)&utlo, g_Utlo);
    cudaGetSymbolAddress((void**)&wthi, g_Wthi);
    cudaGetSymbolAddress((void**)&wtlo, g_Wtlo);

    split_act_kernel<<<(BATCH * DIN / 4 + 255) / 256, 256>>>(X, xhi, xlo, BATCH * DIN / 4);
    split_act_kernel<<<(BATCH * HH / 4 + 255) / 256, 256>>>(Hin, hhi, hlo, BATCH * HH / 4);
    split_w_kernel<DIN><<<(4 * HH * DIN + 255) / 256, 256>>>(U, uthi, utlo);
    split_w_kernel<HH> <<<(4 * HH * HH + 255) / 256, 256>>>(W, wthi, wtlo);
    bias_kernel<<<8, 256>>>(bU, bW);

    dim3 grid(HH / 32, BATCH / BM);   // (16, 512)
    lstm_mma_kernel<<<grid, 256, SMEM_TOTAL>>>(Cin, out);
}

// round 6
// speedup vs baseline: 9.2600x; 2.2401x over previous
#include <cuda_runtime.h>
#include <cuda_fp16.h>
#include <cstdint>

// ============================================================================
// LSTM cell via mma.sync fp16 single-pass (fp32 accum), fused LSTM epilogue.
// B=65536, Din=256, H=512 fixed.
// CTA: 128 batch x 128 cols (4 gates x 32 h). 8 warps (2M x 4N), warp 64x32.
// K pipeline: BK=64, 3-stage cp.async, 12 stages = 4 (x@U) + 8 (h@W).
// Error budget: fp16 rounding -> predicted rel_err ~4e-4 < 1e-3 (validated
// rounding model from bf16-3-pass round: predicted 5e-6, measured 4.95e-6).
// ============================================================================

#define BATCH 65536
#define DIN   256
#define HH    512
#define BM    128
#define BK    64
#define NSTAGE 12

// ---------------- device scratch --------------------------------------------
__device__ __half g_Xh[BATCH * DIN];
__device__ __half g_Hh[BATCH * HH];
__device__ __half g_Ut[4 * HH * DIN];   // [g][h][k] K-major
__device__ __half g_Wt[4 * HH * HH];
__device__ float  g_bias[4 * HH];        // bU + bW

// ---------------- helpers ----------------------------------------------------
__device__ __forceinline__ uint32_t smem_u32(const void* p) {
    uint32_t a;
    asm("{ .reg .u64 t; cvta.to.shared.u64 t, %1; cvt.u32.u64 %0, t; }"
        : "=r"(a) : "l"(p));
    return a;
}
#define SW128(off) ((off) ^ (((off) >> 3) & 0x70))

__device__ __forceinline__ void cp16(uint32_t dst, const void* src) {
    asm volatile("cp.async.cg.shared.global [%0], [%1], 16;\n" :: "r"(dst), "l"(src));
}
#define CP_COMMIT() asm volatile("cp.async.commit_group;\n" ::: "memory")
#define CP_WAIT2()  asm volatile("cp.async.wait_group 2;\n" ::: "memory")
#define CP_WAIT1()  asm volatile("cp.async.wait_group 1;\n" ::: "memory")
#define CP_WAIT0()  asm volatile("cp.async.wait_group 0;\n" ::: "memory")

#define LDSM_X4(r0, r1, r2, r3, a)                                              \
    asm volatile("ldmatrix.sync.aligned.m8n8.x4.shared.b16 {%0,%1,%2,%3}, [%4];"\
        : "=r"(r0), "=r"(r1), "=r"(r2), "=r"(r3) : "r"(a))

__device__ __forceinline__ void mma16816(float* c, uint32_t a0, uint32_t a1,
                                         uint32_t a2, uint32_t a3,
                                         uint32_t b0, uint32_t b1) {
    asm volatile(
        "mma.sync.aligned.m16n8k16.row.col.f32.f16.f16.f32 "
        "{%0,%1,%2,%3}, {%4,%5,%6,%7}, {%8,%9}, {%0,%1,%2,%3};"
        : "+f"(c[0]), "+f"(c[1]), "+f"(c[2]), "+f"(c[3])
        : "r"(a0), "r"(a1), "r"(a2), "r"(a3), "r"(b0), "r"(b1));
}

// ---------------- SMEM layout ------------------------------------------------
// [0, 512)      bias (4 gates x 32 h floats)
// [1024, ...)   3 stage buffers; per stage: A 16KB + B 16KB = 32KB
// epilogue reuses [1024, 1024+73728): 4 planes of 128 x 36 floats
#define SM_STAGE(b) (1024 + (b) * 32768)
#define SMEM_TOTAL  (1024 + 3 * 32768)   // 99328
#define EP_BASE     1024
#define EP_PLANE    18432                // 128 * 36 * 4
#define EP_ROW      144                  // 36 floats

// ---------------- conversion kernels -----------------------------------------
__global__ void conv_act_kernel(const float* __restrict__ src,
                                __half* __restrict__ dst, int n4) {
    int i = blockIdx.x * blockDim.x + threadIdx.x;
    if (i >= n4) return;
    float4 v = reinterpret_cast<const float4*>(src)[i];
    __half h[4] = {__float2half_rn(v.x), __float2half_rn(v.y),
                   __float2half_rn(v.z), __float2half_rn(v.w)};
    reinterpret_cast<uint2*>(dst)[i] = *reinterpret_cast<uint2*>(h);
}

template<int K>
__global__ void conv_w_kernel(const float* __restrict__ src,   // [4, K, HH]
                              __half* __restrict__ dst) {      // [4, HH, K]
    int i = blockIdx.x * blockDim.x + threadIdx.x;
    if (i >= 4 * HH * K) return;
    int k = i % K;
    int h = (i / K) % HH;
    int g = i / (K * HH);
    dst[i] = __float2half_rn(src[((size_t)g * K + k) * HH + h]);
}

__global__ void bias_kernel(const float* __restrict__ bU, const float* __restrict__ bW) {
    int i = blockIdx.x * blockDim.x + threadIdx.x;
    if (i < 4 * HH) g_bias[i] = bU[i] + bW[i];
}

// ---------------- stage source selection -------------------------------------
__device__ __forceinline__ void stage_src(int s, const __half*& A,
                                          const __half*& Bt, int& K, int& k0) {
    if (s < 4) {
        K = DIN; k0 = s * BK;
        A = g_Xh; Bt = g_Ut;
    } else {
        K = HH; k0 = (s - 4) * BK;
        A = g_Hh; Bt = g_Wt;
    }
}

__device__ __forceinline__ void load_stage(uint32_t smem_base, int buf, int s,
                                           int bm0, int h0, int tid) {
    const __half *A, *Bt;
    int K, k0;
    stage_src(s, A, Bt, K, k0);
    uint32_t abase = smem_base + SM_STAGE(buf);
    // A tile: 128 rows x 64 k (128B/row), SW128
    #pragma unroll
    for (int i = 0; i < 4; i++) {
        int c = tid + i * 256;        // 0..1023 16B chunks
        int row = c >> 3, o = c & 7;
        cp16(abase + SW128(row * 128 + o * 16),
             A + (size_t)(bm0 + row) * K + k0 + o * 8);
    }
    // B tile: 128 rows (gate-major: row = g*32 + h_local) x 64 k
    uint32_t bbase = abase + 16384;
    #pragma unroll
    for (int i = 0; i < 4; i++) {
        int c = tid + i * 256;
        int row = c >> 3, o = c & 7;
        int g = row >> 5, hl = row & 31;
        cp16(bbase + SW128(row * 128 + o * 16),
             Bt + ((size_t)g * HH + h0 + hl) * K + k0 + o * 8);
    }
    CP_COMMIT();
}

// ---------------- main kernel -------------------------------------------------
__device__ __forceinline__ float sigmoid_f(float x) { return 1.0f / (1.0f + __expf(-x)); }
__device__ __forceinline__ float tanh_f(float x) {
    float ax = fabsf(x);
    float e = __expf(-2.0f * ax);
    float t = (1.0f - e) / (1.0f + e);
    return (x < 0.0f) ? -t : t;
}

__global__ void __launch_bounds__(256, 2)
lstm_mma_kernel(const float* __restrict__ Cin, float* __restrict__ out) {
    extern __shared__ char smem[];
    uint32_t smem_base = smem_u32(smem);
    float* bias_s = reinterpret_cast<float*>(smem);

    const int tid  = threadIdx.x;
    const int lane = tid & 31;
    const int w    = tid >> 5;
    const int wm   = (w >> 2) * 64;     // warp M offset
    const int nb   = (w & 3) * 32;      // warp N offset == gate*32
    const int h0   = blockIdx.x * 32;
    const int bm0  = blockIdx.y * BM;

    if (tid < 128)
        bias_s[tid] = g_bias[(tid >> 5) * HH + h0 + (tid & 31)];

    float acc[4][4][4];
    #pragma unroll
    for (int mi = 0; mi < 4; mi++)
        #pragma unroll
        for (int ni = 0; ni < 4; ni++)
            #pragma unroll
            for (int j = 0; j < 4; j++)
                acc[mi][ni][j] = 0.0f;

    // per-lane ldmatrix base offsets (bytes within tile, pre-swizzle)
    const int ar = wm + (lane & 15);
    const int aco = (lane >> 4) * 16;
    int offA[4];
    #pragma unroll
    for (int mi = 0; mi < 4; mi++)
        offA[mi] = (ar + mi * 16) * 128 + aco;
    const int grp = lane >> 3;
    const int br = nb + (grp >> 1) * 8 + (lane & 7);
    const int bco = (grp & 1) * 16;
    int offB[2];
    #pragma unroll
    for (int j = 0; j < 2; j++)
        offB[j] = (br + j * 16) * 128 + bco;

    // prologue
    load_stage(smem_base, 0, 0, bm0, h0, tid);
    load_stage(smem_base, 1, 1, bm0, h0, tid);
    load_stage(smem_base, 2, 2, bm0, h0, tid);

    int buf = 0;
    for (int s = 0; s < NSTAGE; s++) {
        if (s + 2 < NSTAGE) CP_WAIT2();
        else if (s + 1 < NSTAGE) CP_WAIT1();
        else CP_WAIT0();
        __syncthreads();

        uint32_t ab = smem_base + SM_STAGE(buf);
        uint32_t bb = ab + 16384;
        #pragma unroll
        for (int ks = 0; ks < 4; ks++) {
            uint32_t a[4][4];
            #pragma unroll
            for (int mi = 0; mi < 4; mi++)
                LDSM_X4(a[mi][0], a[mi][1], a[mi][2], a[mi][3],
                        ab + SW128(offA[mi] + ks * 32));
            uint32_t b[2][4];
            #pragma unroll
            for (int j = 0; j < 2; j++)
                LDSM_X4(b[j][0], b[j][1], b[j][2], b[j][3],
                        bb + SW128(offB[j] + ks * 32));
            #pragma unroll
            for (int mi = 0; mi < 4; mi++)
                #pragma unroll
                for (int nt = 0; nt < 4; nt++)
                    mma16816(acc[mi][nt],
                             a[mi][0], a[mi][1], a[mi][2], a[mi][3],
                             b[nt >> 1][(nt & 1) * 2], b[nt >> 1][(nt & 1) * 2 + 1]);
        }
        __syncthreads();
        if (s + 3 < NSTAGE)
            load_stage(smem_base, buf, s + 3, bm0, h0, tid);
        buf = (buf == 2) ? 0 : buf + 1;
    }

    // ---------------- epilogue ------------------------------------------------
    // 1) exchange gates via SMEM planes: Ep[g][m][h] (row stride 36 floats)
    {
        const int g = w & 3;
        char* ep = smem + EP_BASE + g * EP_PLANE;
        #pragma unroll
        for (int mi = 0; mi < 4; mi++) {
            #pragma unroll
            for (int nt = 0; nt < 4; nt++) {
                int row = wm + mi * 16 + (lane >> 2);
                int col = nt * 8 + (lane & 3) * 2;
                *reinterpret_cast<float2*>(ep + row * EP_ROW + col * 4) =
                    make_float2(acc[mi][nt][0], acc[mi][nt][1]);
                *reinterpret_cast<float2*>(ep + (row + 8) * EP_ROW + col * 4) =
                    make_float2(acc[mi][nt][2], acc[mi][nt][3]);
            }
        }
    }
    __syncthreads();

    // 2) LSTM update: thread t handles m = t/2, h = (t&1)*16 .. +16
    {
        const int m_loc = tid >> 1;
        const int hb = (tid & 1) * 16;
        const int m = bm0 + m_loc;
        const size_t BHo = (size_t)BATCH * HH;
        const char* ep = smem + EP_BASE;
        #pragma unroll
        for (int hq = 0; hq < 4; hq++) {
            const int h = hb + hq * 4;
            float4 gi = *reinterpret_cast<const float4*>(ep + 0 * EP_PLANE + m_loc * EP_ROW + h * 4);
            float4 gf = *reinterpret_cast<const float4*>(ep + 1 * EP_PLANE + m_loc * EP_ROW + h * 4);
            float4 go = *reinterpret_cast<const float4*>(ep + 2 * EP_PLANE + m_loc * EP_ROW + h * 4);
            float4 gc = *reinterpret_cast<const float4*>(ep + 3 * EP_PLANE + m_loc * EP_ROW + h * 4);
            float4 co = *reinterpret_cast<const float4*>(&Cin[(size_t)m * HH + h0 + h]);
            float vi[4] = {gi.x, gi.y, gi.z, gi.w};
            float vf[4] = {gf.x, gf.y, gf.z, gf.w};
            float vo[4] = {go.x, go.y, go.z, go.w};
            float vc[4] = {gc.x, gc.y, gc.z, gc.w};
            float vold[4] = {co.x, co.y, co.z, co.w};
            float hn[4], cn[4];
            #pragma unroll
            for (int j = 0; j < 4; j++) {
                int cj = h + j;
                float it = sigmoid_f(vi[j] + bias_s[0 * 32 + cj]);
                float ft = sigmoid_f(vf[j] + bias_s[1 * 32 + cj]);
                float ot = sigmoid_f(vo[j] + bias_s[2 * 32 + cj]);
                float ct = tanh_f(vc[j] + bias_s[3 * 32 + cj]);
                float c  = fmaf(it, ct, ft * vold[j]);
                cn[j] = c;
                hn[j] = ot * tanh_f(c);
            }
            *reinterpret_cast<float4*>(&out[(size_t)m * HH + h0 + h]) =
                make_float4(hn[0], hn[1], hn[2], hn[3]);
            *reinterpret_cast<float4*>(&out[BHo + (size_t)m * HH + h0 + h]) =
                make_float4(cn[0], cn[1], cn[2], cn[3]);
        }
    }
}

// ---------------- launch ------------------------------------------------------
extern "C" void kernel_launch(void* const* d_in, const int* in_sizes, int n_in,
                              void* d_out, int out_size) {
    const float* X   = (const float*)d_in[0];
    const float* Hin = (const float*)d_in[1];
    const float* Cin = (const float*)d_in[2];
    const float* U   = (const float*)d_in[3];
    const float* bU  = (const float*)d_in[4];
    const float* W   = (const float*)d_in[5];
    const float* bW  = (const float*)d_in[6];
    float* out = (float*)d_out;

    cudaFuncSetAttribute(lstm_mma_kernel,
                         cudaFuncAttributeMaxDynamicSharedMemorySize, SMEM_TOTAL);

    __half *xh, *hh, *ut, *wt;
    cudaGetSymbolAddress((void**)&xh, g_Xh);
    cudaGetSymbolAddress((void**)&hh, g_Hh);
    cudaGetSymbolAddress((void**)&ut, g_Ut);
    cudaGetSymbolAddress((void**)&wt, g_Wt);

    conv_act_kernel<<<(BATCH * DIN / 4 + 255) / 256, 256>>>(X, xh, BATCH * DIN / 4);
    conv_act_kernel<<<(BATCH * HH / 4 + 255) / 256, 256>>>(Hin, hh, BATCH * HH / 4);
    conv_w_kernel<DIN><<<(4 * HH * DIN + 255) / 256, 256>>>(U, ut);
    conv_w_kernel<HH> <<<(4 * HH * HH + 255) / 256, 256>>>(W, wt);
    bias_kernel<<<8, 256>>>(bU, bW);

    dim3 grid(HH / 32, BATCH / BM);   // (16, 512)
    lstm_mma_kernel<<<grid, 256, SMEM_TOTAL>>>(Cin, out);
}